// round 2
// baseline (speedup 1.0000x reference)
#include <cuda_runtime.h>
#include <cstddef>

#define BATCH 8192

// ---------------- scratch (static device globals; no allocation) ----------------
__device__ float g_h1[BATCH * 32 * 144];   // enc stage1 pooled [B,32,12,12]
__device__ float g_h2[BATCH * 64 * 36];    // enc stage2 pooled [B,64,6,6]
__device__ float g_h3[BATCH * 1152];       // enc stage3 pooled flat [B,128*3*3]
__device__ float g_z[BATCH * 128];         // latent
__device__ float g_scores[BATCH * 1024];   // z @ cb^T
__device__ float g_zq[BATCH * 128];        // quantized latent
__device__ float g_d0[BATCH * 1152];       // dec fc out [B,128,3,3]
__device__ float g_d1[BATCH * 64 * 36];    // dec stage1 upsampled [B,64,6,6]
__device__ float g_d2[BATCH * 32 * 144];   // dec stage2 upsampled [B,32,12,12]
__device__ float g_cnorm[1024];            // |c_j|^2

// ================= conv1 (1->32, 24x24) + relu + pool -> [B,32,12,12] =================
__global__ __launch_bounds__(256) void k_conv1(const float* __restrict__ x,
                                               const float* __restrict__ w,
                                               const float* __restrict__ b) {
    __shared__ float sIn[26 * 26];
    __shared__ float sW[32 * 9];
    __shared__ float sB[32];
    int img = blockIdx.x;
    int tid = threadIdx.x;
    for (int i = tid; i < 26 * 26; i += 256) sIn[i] = 0.f;
    for (int i = tid; i < 288; i += 256) sW[i] = w[i];
    if (tid < 32) sB[tid] = b[tid];
    __syncthreads();
    const float* xi = x + (size_t)img * 576;
    for (int i = tid; i < 576; i += 256) {
        int y = i / 24, xx = i - y * 24;
        sIn[(y + 1) * 26 + xx + 1] = xi[i];
    }
    __syncthreads();
    int c = tid >> 3;
    float wr[9];
#pragma unroll
    for (int k = 0; k < 9; k++) wr[k] = sW[c * 9 + k];
    float bias = sB[c];
    float* outp = g_h1 + (size_t)img * 32 * 144 + (size_t)c * 144;
    for (int p = (tid & 7); p < 144; p += 8) {
        int py = p / 12, px = p - py * 12;
        float in4[4][4];
#pragma unroll
        for (int dy = 0; dy < 4; dy++)
#pragma unroll
            for (int dx = 0; dx < 4; dx++)
                in4[dy][dx] = sIn[(2 * py + dy) * 26 + 2 * px + dx];
        float m = 0.f;  // pool of relu == relu of max; all relu >= 0
#pragma unroll
        for (int dy = 0; dy < 2; dy++)
#pragma unroll
            for (int dx = 0; dx < 2; dx++) {
                float s = bias;
#pragma unroll
                for (int ky = 0; ky < 3; ky++)
#pragma unroll
                    for (int kx = 0; kx < 3; kx++)
                        s = fmaf(in4[dy + ky][dx + kx], wr[ky * 3 + kx], s);
                m = fmaxf(m, s);
            }
        outp[p] = m;
    }
}

// ================= conv2 (32->64, 12x12) + relu + pool -> [B,64,6,6] =================
// 1 image/block, 288 threads: thread = (octile of 8 oc) x (pooled pos of 36)
__global__ __launch_bounds__(288) void k_conv2(const float* __restrict__ w,
                                               const float* __restrict__ b) {
    extern __shared__ float sm[];
    float* sIn = sm;               // 32 * 196 = 6272  (14x14 padded per ic)
    float* sW  = sm + 6272;        // 64 * 289 = 18496 (pitch 289 kills bank conflicts)
    float* sB  = sW + 18496;       // 64
    int img = blockIdx.x;
    int tid = threadIdx.x;
    for (int i = tid; i < 6272; i += 288) sIn[i] = 0.f;
    for (int i = tid; i < 64 * 288; i += 288) {
        int oc = i / 288, r = i - oc * 288;
        sW[oc * 289 + r] = w[i];
    }
    if (tid < 64) sB[tid] = b[tid];
    __syncthreads();
    const float* in = g_h1 + (size_t)img * 32 * 144;
    for (int i = tid; i < 32 * 144; i += 288) {
        int c = i / 144, r = i - c * 144;
        int y = r / 12, xx = r - y * 12;
        sIn[c * 196 + (y + 1) * 14 + xx + 1] = in[i];
    }
    __syncthreads();
    int octile = tid & 7;
    int p = tid >> 3;                  // 0..35
    int py = p / 6, px = p - py * 6;
    int y0 = 2 * py, x0 = 2 * px;
    float acc[4][8];
#pragma unroll
    for (int q = 0; q < 4; q++)
#pragma unroll
        for (int u = 0; u < 8; u++) acc[q][u] = 0.f;
    const float* swp = sW + octile * 8 * 289;
    for (int ic = 0; ic < 32; ic++) {
        const float* sip = sIn + ic * 196;
#pragma unroll
        for (int k = 0; k < 9; k++) {
            int ky = k / 3, kx = k - ky * 3;
            float wv[8];
#pragma unroll
            for (int u = 0; u < 8; u++) wv[u] = swp[u * 289 + ic * 9 + k];
            const float* row = sip + (y0 + ky) * 14 + x0 + kx;
            float i00 = row[0], i01 = row[1], i10 = row[14], i11 = row[15];
#pragma unroll
            for (int u = 0; u < 8; u++) {
                acc[0][u] = fmaf(i00, wv[u], acc[0][u]);
                acc[1][u] = fmaf(i01, wv[u], acc[1][u]);
                acc[2][u] = fmaf(i10, wv[u], acc[2][u]);
                acc[3][u] = fmaf(i11, wv[u], acc[3][u]);
            }
        }
    }
    float* outp = g_h2 + (size_t)img * 64 * 36;
#pragma unroll
    for (int u = 0; u < 8; u++) {
        int oc = octile * 8 + u;
        float m = fmaxf(fmaxf(acc[0][u], acc[1][u]), fmaxf(acc[2][u], acc[3][u])) + sB[oc];
        outp[oc * 36 + p] = fmaxf(m, 0.f);
    }
}

// ================= conv3 (64->128, 6x6) + relu + pool -> [B,128,3,3] =================
// 8 images/block, oc chunks of 32, 288 threads: (img 8) x (octile 4) x (pooled 9)
__global__ __launch_bounds__(288) void k_conv3(const float* __restrict__ w,
                                               const float* __restrict__ b) {
    extern __shared__ float sm[];
    float* sIn = sm;               // 8 * 64 * 64 = 32768 (8x8 padded per ic)
    float* sW  = sm + 32768;       // 32 * 577 = 18464
    float* sB  = sW + 18464;       // 128
    int blk = blockIdx.x;
    int tid = threadIdx.x;
    for (int i = tid; i < 32768; i += 288) sIn[i] = 0.f;
    if (tid < 128) sB[tid] = b[tid];
    __syncthreads();
    for (int i = tid; i < 8 * 64 * 36; i += 288) {
        int im = i / 2304;
        int r = i - im * 2304;
        int c = r / 36, rr = r - c * 36;
        int y = rr / 6, xx = rr - y * 6;
        sIn[im * 4096 + c * 64 + (y + 1) * 8 + xx + 1] = g_h2[(size_t)(blk * 8 + im) * 2304 + r];
    }
    int im = tid / 36;
    int r = tid - im * 36;
    int octile = r & 3;
    int p = r >> 2;                 // 0..8
    int py = p / 3, px = p - py * 3;
    int y0 = 2 * py, x0 = 2 * px;
    const float* sip0 = sIn + im * 4096;
    float* outp = g_h3 + (size_t)(blk * 8 + im) * 1152;
    for (int chunk = 0; chunk < 4; chunk++) {
        __syncthreads();
        for (int i = tid; i < 32 * 576; i += 288) {
            int ocl = i / 576, rr = i - ocl * 576;
            sW[ocl * 577 + rr] = w[(chunk * 32 + ocl) * 576 + rr];
        }
        __syncthreads();
        float acc[4][8];
#pragma unroll
        for (int q = 0; q < 4; q++)
#pragma unroll
            for (int u = 0; u < 8; u++) acc[q][u] = 0.f;
        const float* swp = sW + octile * 8 * 577;
        for (int ic = 0; ic < 64; ic++) {
            const float* sip = sip0 + ic * 64;
#pragma unroll
            for (int k = 0; k < 9; k++) {
                int ky = k / 3, kx = k - ky * 3;
                float wv[8];
#pragma unroll
                for (int u = 0; u < 8; u++) wv[u] = swp[u * 577 + ic * 9 + k];
                const float* row = sip + (y0 + ky) * 8 + x0 + kx;
                float i00 = row[0], i01 = row[1], i10 = row[8], i11 = row[9];
#pragma unroll
                for (int u = 0; u < 8; u++) {
                    acc[0][u] = fmaf(i00, wv[u], acc[0][u]);
                    acc[1][u] = fmaf(i01, wv[u], acc[1][u]);
                    acc[2][u] = fmaf(i10, wv[u], acc[2][u]);
                    acc[3][u] = fmaf(i11, wv[u], acc[3][u]);
                }
            }
        }
#pragma unroll
        for (int u = 0; u < 8; u++) {
            int oc = chunk * 32 + octile * 8 + u;
            float m = fmaxf(fmaxf(acc[0][u], acc[1][u]), fmaxf(acc[2][u], acc[3][u])) + sB[oc];
            outp[oc * 9 + p] = fmaxf(m, 0.f);
        }
    }
}

// ================= generic NT SGEMM: C[M,N] = A[M,K] * B[N,K]^T (+bias) =================
// BM=BN=64, BK=16, 256 threads, 4x4 micro-tile
__global__ __launch_bounds__(256) void k_gemm_nt(const float* __restrict__ A,
                                                 const float* __restrict__ Bm,
                                                 const float* __restrict__ bias,
                                                 float* __restrict__ C,
                                                 int N, int K, int useBias) {
    __shared__ float As[16][68];
    __shared__ float Bs[16][68];
    int m0 = blockIdx.x * 64;
    int n0 = blockIdx.y * 64;
    int tid = threadIdx.x;
    int lr = tid >> 2;
    int lk = (tid & 3) << 2;
    int tx = tid & 15, ty = tid >> 4;
    float acc[4][4];
#pragma unroll
    for (int i = 0; i < 4; i++)
#pragma unroll
        for (int j = 0; j < 4; j++) acc[i][j] = 0.f;
    const float* aPtr = A + (size_t)(m0 + lr) * K + lk;
    const float* bPtr = Bm + (size_t)(n0 + lr) * K + lk;
    for (int k0 = 0; k0 < K; k0 += 16) {
        float4 av = *(const float4*)(aPtr + k0);
        float4 bv = *(const float4*)(bPtr + k0);
        __syncthreads();
        As[lk + 0][lr] = av.x; As[lk + 1][lr] = av.y; As[lk + 2][lr] = av.z; As[lk + 3][lr] = av.w;
        Bs[lk + 0][lr] = bv.x; Bs[lk + 1][lr] = bv.y; Bs[lk + 2][lr] = bv.z; Bs[lk + 3][lr] = bv.w;
        __syncthreads();
#pragma unroll
        for (int kk = 0; kk < 16; kk++) {
            float4 a = *(const float4*)&As[kk][ty * 4];
            float4 bq = *(const float4*)&Bs[kk][tx * 4];
            float ar[4] = {a.x, a.y, a.z, a.w};
            float br[4] = {bq.x, bq.y, bq.z, bq.w};
#pragma unroll
            for (int i = 0; i < 4; i++)
#pragma unroll
                for (int j = 0; j < 4; j++)
                    acc[i][j] = fmaf(ar[i], br[j], acc[i][j]);
        }
    }
#pragma unroll
    for (int i = 0; i < 4; i++) {
        int m = m0 + ty * 4 + i;
#pragma unroll
        for (int j = 0; j < 4; j++) {
            int n = n0 + tx * 4 + j;
            float v = acc[i][j];
            if (useBias) v += bias[n];
            C[(size_t)m * N + n] = v;
        }
    }
}

// ================= codebook norms =================
__global__ void k_cnorm(const float* __restrict__ cb) {
    int j = blockIdx.x * blockDim.x + threadIdx.x;
    if (j < 1024) {
        float s = 0.f;
        const float* c = cb + (size_t)j * 128;
#pragma unroll 8
        for (int k = 0; k < 128; k++) s = fmaf(c[k], c[k], s);
        g_cnorm[j] = s;
    }
}

// ================= argmin over codewords + gather z_q =================
__global__ __launch_bounds__(128) void k_argmin_gather(const float* __restrict__ cb) {
    __shared__ float sv[128];
    __shared__ int si[128];
    int img = blockIdx.x;
    int tid = threadIdx.x;
    const float* srow = g_scores + (size_t)img * 1024;
    float best = 3.4e38f;
    int bi = 0;
    for (int j = tid; j < 1024; j += 128) {
        float v = g_cnorm[j] - 2.f * srow[j];
        if (v < best) { best = v; bi = j; }
    }
    sv[tid] = best; si[tid] = bi;
    __syncthreads();
    for (int s = 64; s > 0; s >>= 1) {
        if (tid < s) {
            float v2 = sv[tid + s]; int i2 = si[tid + s];
            if (v2 < sv[tid] || (v2 == sv[tid] && i2 < si[tid])) { sv[tid] = v2; si[tid] = i2; }
        }
        __syncthreads();
    }
    int idx = si[0];
    g_zq[(size_t)img * 128 + tid] = cb[(size_t)idx * 128 + tid];
}

// ================= dct1 (128->64, 3x3) conv-transpose + relu + up2 -> [B,64,6,6] =================
// 16 images/block, oc chunks of 32, 192 threads: (img 16) x (octile 4) x (row 3)
__global__ __launch_bounds__(192) void k_dct1(const float* __restrict__ w,
                                              const float* __restrict__ b) {
    extern __shared__ float sm[];
    float* sIn = sm;                // 16 * 1152 = 18432 (unpadded [128,3,3])
    float* sW  = sm + 18432;        // 32 * 1153 = 36896
    float* sB  = sW + 36896;        // 64
    int blk = blockIdx.x;           // 512
    int tid = threadIdx.x;
    for (int i = tid; i < 16 * 1152; i += 192)
        sIn[i] = g_d0[(size_t)blk * 16 * 1152 + i];
    if (tid < 64) sB[tid] = b[tid];
    int im = tid / 12;
    int r = tid - im * 12;
    int octile = r & 3;
    int y = r >> 2;                 // 0..2
    const float* sip = sIn + im * 1152;
    for (int chunk = 0; chunk < 2; chunk++) {
        __syncthreads();
        // effective conv weight: w_eff[o][i][k] = w[i][o][8-k]  (flip + transpose)
        for (int i = tid; i < 32 * 1152; i += 192) {
            int ocl = i / 1152, rr = i - ocl * 1152;
            int ic = rr / 9, k = rr - ic * 9;
            sW[ocl * 1153 + rr] = w[ic * 576 + (chunk * 32 + ocl) * 9 + (8 - k)];
        }
        __syncthreads();
        float acc[3][8];
#pragma unroll
        for (int xq = 0; xq < 3; xq++)
#pragma unroll
            for (int u = 0; u < 8; u++) acc[xq][u] = 0.f;
        const float* swp = sW + octile * 8 * 1153;
        for (int ic = 0; ic < 128; ic++) {
#pragma unroll
            for (int ky = 0; ky < 3; ky++) {
                int yy = y + ky - 1;
                bool rowv = (yy >= 0) && (yy < 3);
                float in5[5];
#pragma unroll
                for (int j = 0; j < 5; j++) {
                    int xx = j - 1;
                    in5[j] = (rowv && xx >= 0 && xx < 3) ? sip[ic * 9 + yy * 3 + xx] : 0.f;
                }
                float wv[3][8];
#pragma unroll
                for (int kx = 0; kx < 3; kx++)
#pragma unroll
                    for (int u = 0; u < 8; u++)
                        wv[kx][u] = swp[u * 1153 + ic * 9 + ky * 3 + kx];
#pragma unroll
                for (int xq = 0; xq < 3; xq++)
#pragma unroll
                    for (int kx = 0; kx < 3; kx++)
#pragma unroll
                        for (int u = 0; u < 8; u++)
                            acc[xq][u] = fmaf(in5[xq + kx], wv[kx][u], acc[xq][u]);
            }
        }
        float* outBase = g_d1 + (size_t)(blk * 16 + im) * 64 * 36;
#pragma unroll
        for (int u = 0; u < 8; u++) {
            int oc = chunk * 32 + octile * 8 + u;
            float bi = sB[oc];
            float* o = outBase + (size_t)oc * 36;
#pragma unroll
            for (int xq = 0; xq < 3; xq++) {
                float v = fmaxf(acc[xq][u] + bi, 0.f);
                int rb = (2 * y) * 6 + 2 * xq;
                o[rb] = v; o[rb + 1] = v; o[rb + 6] = v; o[rb + 7] = v;
            }
        }
    }
}

// ================= dct2 (64->32, 6x6) conv-transpose + relu + up2 -> [B,32,12,12] =================
// 8 images/block, 192 threads: (img 8) x (octile 4) x (row 6)
__global__ __launch_bounds__(192) void k_dct2(const float* __restrict__ w,
                                              const float* __restrict__ b) {
    extern __shared__ float sm[];
    float* sIn = sm;                // 8 * 2304 = 18432
    float* sW  = sm + 18432;        // 32 * 577 = 18464
    float* sB  = sW + 18464;        // 32
    int blk = blockIdx.x;           // 1024
    int tid = threadIdx.x;
    for (int i = tid; i < 8 * 2304; i += 192)
        sIn[i] = g_d1[(size_t)blk * 8 * 2304 + i];
    for (int i = tid; i < 32 * 576; i += 192) {
        int o = i / 576, rr = i - o * 576;
        int ic = rr / 9, k = rr - ic * 9;
        sW[o * 577 + rr] = w[ic * 288 + o * 9 + (8 - k)];
    }
    if (tid < 32) sB[tid] = b[tid];
    __syncthreads();
    int im = tid / 24;
    int r = tid - im * 24;
    int octile = r & 3;
    int y = r >> 2;                 // 0..5
    const float* sip = sIn + im * 2304;
    float acc[6][8];
#pragma unroll
    for (int xq = 0; xq < 6; xq++)
#pragma unroll
        for (int u = 0; u < 8; u++) acc[xq][u] = 0.f;
    const float* swp = sW + octile * 8 * 577;
    for (int ic = 0; ic < 64; ic++) {
#pragma unroll
        for (int ky = 0; ky < 3; ky++) {
            int yy = y + ky - 1;
            bool rowv = (yy >= 0) && (yy < 6);
            float in8[8];
#pragma unroll
            for (int j = 0; j < 8; j++) {
                int xx = j - 1;
                in8[j] = (rowv && xx >= 0 && xx < 6) ? sip[ic * 36 + yy * 6 + xx] : 0.f;
            }
            float wv[3][8];
#pragma unroll
            for (int kx = 0; kx < 3; kx++)
#pragma unroll
                for (int u = 0; u < 8; u++)
                    wv[kx][u] = swp[u * 577 + ic * 9 + ky * 3 + kx];
#pragma unroll
            for (int xq = 0; xq < 6; xq++)
#pragma unroll
                for (int kx = 0; kx < 3; kx++)
#pragma unroll
                    for (int u = 0; u < 8; u++)
                        acc[xq][u] = fmaf(in8[xq + kx], wv[kx][u], acc[xq][u]);
        }
    }
#pragma unroll
    for (int u = 0; u < 8; u++) {
        int oc = octile * 8 + u;
        float bi = sB[oc];
        float* o = g_d2 + ((size_t)(blk * 8 + im) * 32 + oc) * 144;
#pragma unroll
        for (int xq = 0; xq < 6; xq++) {
            float v = fmaxf(acc[xq][u] + bi, 0.f);
            int rb = (2 * y) * 12 + 2 * xq;
            o[rb] = v; o[rb + 1] = v; o[rb + 12] = v; o[rb + 13] = v;
        }
    }
}

// ================= dct3 (32->1, 12x12) conv-transpose + relu + up2 -> d_out [B,1,24,24] =================
__global__ __launch_bounds__(192) void k_dct3(const float* __restrict__ w,
                                              const float* __restrict__ b,
                                              float* __restrict__ out) {
    extern __shared__ float sm[];
    float* sIn = sm;                // 8 * 4608 = 36864
    float* sW  = sm + 36864;        // 288
    int blk = blockIdx.x;           // 1024
    int tid = threadIdx.x;
    for (int i = tid; i < 8 * 4608; i += 192)
        sIn[i] = g_d2[(size_t)blk * 8 * 4608 + i];
    // FIX (R1 bug): block has 192 threads, 288 weights -> must grid-stride,
    // the old `if (tid < 288)` left sW[192..287] uninitialized.
    for (int i = tid; i < 288; i += 192) {
        int ic = i / 9, k = i - ic * 9;
        sW[ic * 9 + k] = w[ic * 9 + (8 - k)];
    }
    __syncthreads();
    float b0 = b[0];
    int im = tid / 24;
    int r = tid - im * 24;
    int y = r >> 1;                 // 0..11
    int xh = (r & 1) * 6;           // x base: 0 or 6
    const float* sip = sIn + im * 4608;
    float acc[6];
#pragma unroll
    for (int xq = 0; xq < 6; xq++) acc[xq] = 0.f;
    for (int ic = 0; ic < 32; ic++) {
#pragma unroll
        for (int ky = 0; ky < 3; ky++) {
            int yy = y + ky - 1;
            bool rowv = (yy >= 0) && (yy < 12);
            float in8[8];
#pragma unroll
            for (int j = 0; j < 8; j++) {
                int xx = xh + j - 1;
                in8[j] = (rowv && xx >= 0 && xx < 12) ? sip[ic * 144 + yy * 12 + xx] : 0.f;
            }
            float w3[3];
#pragma unroll
            for (int kx = 0; kx < 3; kx++) w3[kx] = sW[ic * 9 + ky * 3 + kx];
#pragma unroll
            for (int xq = 0; xq < 6; xq++)
#pragma unroll
                for (int kx = 0; kx < 3; kx++)
                    acc[xq] = fmaf(in8[xq + kx], w3[kx], acc[xq]);
        }
    }
    float* o = out + (size_t)(blk * 8 + im) * 576;
#pragma unroll
    for (int xq = 0; xq < 6; xq++) {
        float v = fmaxf(acc[xq] + b0, 0.f);
        int gx = xh + xq;
        int rb = (2 * y) * 24 + 2 * gx;
        o[rb] = v; o[rb + 1] = v; o[rb + 24] = v; o[rb + 25] = v;
    }
}

// ================= launcher =================
extern "C" void kernel_launch(void* const* d_in, const int* in_sizes, int n_in,
                              void* d_out, int out_size) {
    (void)in_sizes; (void)n_in; (void)out_size;
    const float* x    = (const float*)d_in[0];
    const float* c1w  = (const float*)d_in[1];
    const float* c1b  = (const float*)d_in[2];
    const float* c2w  = (const float*)d_in[3];
    const float* c2b  = (const float*)d_in[4];
    const float* c3w  = (const float*)d_in[5];
    const float* c3b  = (const float*)d_in[6];
    const float* encw = (const float*)d_in[7];
    const float* encb = (const float*)d_in[8];
    const float* cb   = (const float*)d_in[9];
    const float* decw = (const float*)d_in[10];
    const float* decb = (const float*)d_in[11];
    const float* d1w  = (const float*)d_in[12];
    const float* d1b  = (const float*)d_in[13];
    const float* d2w  = (const float*)d_in[14];
    const float* d2b  = (const float*)d_in[15];
    const float* d3w  = (const float*)d_in[16];
    const float* d3b  = (const float*)d_in[17];
    float* out = (float*)d_out;

    cudaFuncSetAttribute(k_conv2, cudaFuncAttributeMaxDynamicSharedMemorySize, 99328);
    cudaFuncSetAttribute(k_conv3, cudaFuncAttributeMaxDynamicSharedMemorySize, 205440);
    cudaFuncSetAttribute(k_dct1,  cudaFuncAttributeMaxDynamicSharedMemorySize, 221568);
    cudaFuncSetAttribute(k_dct2,  cudaFuncAttributeMaxDynamicSharedMemorySize, 147712);
    cudaFuncSetAttribute(k_dct3,  cudaFuncAttributeMaxDynamicSharedMemorySize, 148608);

    float *p_h3, *p_z, *p_scores, *p_zq, *p_d0;
    cudaGetSymbolAddress((void**)&p_h3, g_h3);
    cudaGetSymbolAddress((void**)&p_z, g_z);
    cudaGetSymbolAddress((void**)&p_scores, g_scores);
    cudaGetSymbolAddress((void**)&p_zq, g_zq);
    cudaGetSymbolAddress((void**)&p_d0, g_d0);

    k_conv1<<<BATCH, 256>>>(x, c1w, c1b);
    k_cnorm<<<4, 256>>>(cb);
    k_conv2<<<BATCH, 288, 99328>>>(c2w, c2b);
    k_conv3<<<BATCH / 8, 288, 205440>>>(c3w, c3b);
    // z = h3 @ encw^T + encb   [8192,1152]x[128,1152]^T
    k_gemm_nt<<<dim3(BATCH / 64, 2), 256>>>(p_h3, encw, encb, p_z, 128, 1152, 1);
    // scores = z @ cb^T        [8192,128]x[1024,128]^T
    k_gemm_nt<<<dim3(BATCH / 64, 16), 256>>>(p_z, cb, nullptr, p_scores, 1024, 128, 0);
    k_argmin_gather<<<BATCH, 128>>>(cb);
    // d0 = zq @ decw^T + decb  [8192,128]x[1152,128]^T
    k_gemm_nt<<<dim3(BATCH / 64, 18), 256>>>(p_zq, decw, decb, p_d0, 1152, 128, 1);
    k_dct1<<<BATCH / 16, 192, 221568>>>(d1w, d1b);
    k_dct2<<<BATCH / 8, 192, 147712>>>(d2w, d2b);
    k_dct3<<<BATCH / 8, 192, 148608>>>(d3w, d3b, out);
}

// round 3
// speedup vs baseline: 1.3210x; 1.3210x over previous
#include <cuda_runtime.h>
#include <cstddef>

#define BATCH 8192

typedef unsigned long long u64;

__device__ __forceinline__ u64 pk2(float lo, float hi) {
    u64 r; asm("mov.b64 %0, {%1,%2};" : "=l"(r) : "f"(lo), "f"(hi)); return r;
}
__device__ __forceinline__ void upk2(u64 v, float& lo, float& hi) {
    asm("mov.b64 {%0,%1}, %2;" : "=f"(lo), "=f"(hi) : "l"(v));
}
__device__ __forceinline__ void ffma2(u64& d, u64 a, u64 b) {
    asm("fma.rn.f32x2 %0, %1, %2, %0;" : "+l"(d) : "l"(a), "l"(b));
}

// ---------------- scratch (static device globals; no allocation) ----------------
__device__ float g_h1[BATCH * 32 * 144];   // enc stage1 pooled [B,32,12,12]
__device__ float g_h2[BATCH * 64 * 36];    // enc stage2 pooled [B,64,6,6]
__device__ float g_h3[BATCH * 1152];       // enc stage3 pooled flat [B,128*3*3]
__device__ float g_z[BATCH * 128];         // latent
__device__ float g_scores[BATCH * 1024];   // z @ cb^T
__device__ float g_zq[BATCH * 128];        // quantized latent
__device__ float g_d1[BATCH * 64 * 36];    // dec stage1 upsampled [B,64,6,6]
__device__ float g_d2[BATCH * 32 * 144];   // dec stage2 upsampled [B,32,12,12]
__device__ float g_cnorm[1024];            // |c_j|^2
__device__ float g_M[576 * 128];           // fused dec_fc + dct1 matrix
__device__ float g_cv[576];                // fused bias for dct1 output

// ================= conv1 (1->32, 24x24) + relu + pool -> [B,32,12,12] =================
__global__ __launch_bounds__(256) void k_conv1(const float* __restrict__ x,
                                               const float* __restrict__ w,
                                               const float* __restrict__ b) {
    __shared__ float sIn[26 * 26];
    __shared__ float sW[32 * 9];
    __shared__ float sB[32];
    int img = blockIdx.x;
    int tid = threadIdx.x;
    for (int i = tid; i < 26 * 26; i += 256) sIn[i] = 0.f;
    for (int i = tid; i < 288; i += 256) sW[i] = w[i];
    if (tid < 32) sB[tid] = b[tid];
    __syncthreads();
    const float* xi = x + (size_t)img * 576;
    for (int i = tid; i < 576; i += 256) {
        int y = i / 24, xx = i - y * 24;
        sIn[(y + 1) * 26 + xx + 1] = xi[i];
    }
    __syncthreads();
    int c = tid >> 3;
    float wr[9];
#pragma unroll
    for (int k = 0; k < 9; k++) wr[k] = sW[c * 9 + k];
    float bias = sB[c];
    float* outp = g_h1 + (size_t)img * 32 * 144 + (size_t)c * 144;
    for (int p = (tid & 7); p < 144; p += 8) {
        int py = p / 12, px = p - py * 12;
        float in4[4][4];
#pragma unroll
        for (int dy = 0; dy < 4; dy++)
#pragma unroll
            for (int dx = 0; dx < 4; dx++)
                in4[dy][dx] = sIn[(2 * py + dy) * 26 + 2 * px + dx];
        float m = 0.f;
#pragma unroll
        for (int dy = 0; dy < 2; dy++)
#pragma unroll
            for (int dx = 0; dx < 2; dx++) {
                float s = bias;
#pragma unroll
                for (int ky = 0; ky < 3; ky++)
#pragma unroll
                    for (int kx = 0; kx < 3; kx++)
                        s = fmaf(in4[dy + ky][dx + kx], wr[ky * 3 + kx], s);
                m = fmaxf(m, s);
            }
        outp[p] = m;
    }
}

// ================= conv2 (32->64, 12x12) + relu + pool -> [B,64,6,6] =================
// 1 image/block, 288 threads = (octile of 8 oc: 8) x (pooled pos: 36). f32x2 FMA.
__global__ __launch_bounds__(288, 2) void k_conv2(const float* __restrict__ w,
                                                  const float* __restrict__ b) {
    extern __shared__ float sm[];
    float* sIn = sm;               // 32 * 196 = 6272
    float* sW  = sm + 6272;        // 288 taps * pitch 68 = 19584 ([(ic*9+k)*68 + oc])
    float* sB  = sW + 19584;       // 64
    int img = blockIdx.x;
    int tid = threadIdx.x;
    for (int i = tid; i < 6272; i += 288) sIn[i] = 0.f;
    for (int i = tid; i < 64 * 288; i += 288) {
        int oc = i / 288, k = i - oc * 288;
        sW[k * 68 + oc] = w[i];
    }
    if (tid < 64) sB[tid] = b[tid];
    __syncthreads();
    const float* in = g_h1 + (size_t)img * 32 * 144;
    for (int i = tid; i < 32 * 144; i += 288) {
        int c = i / 144, r = i - c * 144;
        int y = r / 12, xx = r - y * 12;
        sIn[c * 196 + (y + 1) * 14 + xx + 1] = in[i];
    }
    __syncthreads();
    int octile = tid & 7;
    int p = tid >> 3;                  // 0..35
    int py = p / 6, px = p - py * 6;
    int y0 = 2 * py, x0 = 2 * px;
    u64 acc2[4][4];
#pragma unroll
    for (int q = 0; q < 4; q++)
#pragma unroll
        for (int j = 0; j < 4; j++) acc2[q][j] = 0ULL;
    int kbase = octile * 8;
    for (int ic = 0; ic < 32; ic++) {
        const float* sip = sIn + ic * 196;
#pragma unroll
        for (int k = 0; k < 9; k++) {
            int ky = k / 3, kx = k - ky * 3;
            const u64* wq = reinterpret_cast<const u64*>(sW + (ic * 9 + k) * 68 + kbase);
            u64 w01 = wq[0], w23 = wq[1], w45 = wq[2], w67 = wq[3];
            const float* row = sip + (y0 + ky) * 14 + x0 + kx;
            float i00 = row[0], i01 = row[1], i10 = row[14], i11 = row[15];
            u64 p00 = pk2(i00, i00), p01 = pk2(i01, i01);
            u64 p10 = pk2(i10, i10), p11 = pk2(i11, i11);
            ffma2(acc2[0][0], w01, p00); ffma2(acc2[0][1], w23, p00);
            ffma2(acc2[0][2], w45, p00); ffma2(acc2[0][3], w67, p00);
            ffma2(acc2[1][0], w01, p01); ffma2(acc2[1][1], w23, p01);
            ffma2(acc2[1][2], w45, p01); ffma2(acc2[1][3], w67, p01);
            ffma2(acc2[2][0], w01, p10); ffma2(acc2[2][1], w23, p10);
            ffma2(acc2[2][2], w45, p10); ffma2(acc2[2][3], w67, p10);
            ffma2(acc2[3][0], w01, p11); ffma2(acc2[3][1], w23, p11);
            ffma2(acc2[3][2], w45, p11); ffma2(acc2[3][3], w67, p11);
        }
    }
    float* outp = g_h2 + (size_t)img * 64 * 36;
#pragma unroll
    for (int j = 0; j < 4; j++) {
        float l0, h0, l1, h1, l2, h2, l3, h3;
        upk2(acc2[0][j], l0, h0); upk2(acc2[1][j], l1, h1);
        upk2(acc2[2][j], l2, h2); upk2(acc2[3][j], l3, h3);
        int oc = kbase + 2 * j;
        float mlo = fmaxf(fmaxf(l0, l1), fmaxf(l2, l3)) + sB[oc];
        float mhi = fmaxf(fmaxf(h0, h1), fmaxf(h2, h3)) + sB[oc + 1];
        outp[oc * 36 + p] = fmaxf(mlo, 0.f);
        outp[(oc + 1) * 36 + p] = fmaxf(mhi, 0.f);
    }
}

// ================= conv3 (64->128, 6x6) + relu + pool -> [B,128,3,3] =================
// 8 images/block, 576 threads = (img 8) x (octile of 4 oc: 8) x (pooled 9). f32x2 FMA.
__global__ __launch_bounds__(576) void k_conv3(const float* __restrict__ w,
                                               const float* __restrict__ b) {
    extern __shared__ float sm[];
    float* sIn = sm;               // 8 * 64 * 64 = 32768 (8x8 padded per ic)
    float* sW  = sm + 32768;       // 576 taps * pitch 36 = 20736
    float* sB  = sW + 20736;       // 128
    int blk = blockIdx.x;
    int tid = threadIdx.x;
    for (int i = tid; i < 32768; i += 576) sIn[i] = 0.f;
    if (tid < 128) sB[tid] = b[tid];
    __syncthreads();
    for (int i = tid; i < 8 * 64 * 36; i += 576) {
        int im = i / 2304;
        int r = i - im * 2304;
        int c = r / 36, rr = r - c * 36;
        int y = rr / 6, xx = rr - y * 6;
        sIn[im * 4096 + c * 64 + (y + 1) * 8 + xx + 1] = g_h2[(size_t)(blk * 8 + im) * 2304 + r];
    }
    int im = tid / 72;
    int r = tid - im * 72;
    int octile = r & 7;             // 8 octiles of 4 oc within a 32-oc chunk
    int p = r >> 3;                 // 0..8
    int py = p / 3, px = p - py * 3;
    int y0 = 2 * py, x0 = 2 * px;
    const float* sip0 = sIn + im * 4096;
    float* outp = g_h3 + (size_t)(blk * 8 + im) * 1152;
    for (int chunk = 0; chunk < 4; chunk++) {
        __syncthreads();
        for (int i = tid; i < 32 * 576; i += 576) {
            int ocl = i / 576, kk = i - ocl * 576;
            sW[kk * 36 + ocl] = w[(chunk * 32 + ocl) * 576 + kk];
        }
        __syncthreads();
        u64 acc2[4][2];
#pragma unroll
        for (int q = 0; q < 4; q++) { acc2[q][0] = 0ULL; acc2[q][1] = 0ULL; }
        for (int ic = 0; ic < 64; ic++) {
            const float* sip = sip0 + ic * 64;
#pragma unroll
            for (int k = 0; k < 9; k++) {
                int ky = k / 3, kx = k - ky * 3;
                const u64* wq = reinterpret_cast<const u64*>(sW + (ic * 9 + k) * 36) + octile * 2;
                u64 w01 = wq[0], w23 = wq[1];
                const float* row = sip + (y0 + ky) * 8 + x0 + kx;
                float i00 = row[0], i01 = row[1], i10 = row[8], i11 = row[9];
                u64 p00 = pk2(i00, i00), p01 = pk2(i01, i01);
                u64 p10 = pk2(i10, i10), p11 = pk2(i11, i11);
                ffma2(acc2[0][0], w01, p00); ffma2(acc2[0][1], w23, p00);
                ffma2(acc2[1][0], w01, p01); ffma2(acc2[1][1], w23, p01);
                ffma2(acc2[2][0], w01, p10); ffma2(acc2[2][1], w23, p10);
                ffma2(acc2[3][0], w01, p11); ffma2(acc2[3][1], w23, p11);
            }
        }
#pragma unroll
        for (int j = 0; j < 2; j++) {
            float l0, h0, l1, h1, l2, h2, l3, h3;
            upk2(acc2[0][j], l0, h0); upk2(acc2[1][j], l1, h1);
            upk2(acc2[2][j], l2, h2); upk2(acc2[3][j], l3, h3);
            int oc = chunk * 32 + octile * 4 + 2 * j;
            float mlo = fmaxf(fmaxf(l0, l1), fmaxf(l2, l3)) + sB[oc];
            float mhi = fmaxf(fmaxf(h0, h1), fmaxf(h2, h3)) + sB[oc + 1];
            outp[oc * 9 + p] = fmaxf(mlo, 0.f);
            outp[(oc + 1) * 9 + p] = fmaxf(mhi, 0.f);
        }
    }
}

// ================= generic NT SGEMM: C[M,N] = A[M,K] * B[N,K]^T (+bias), f32x2 =================
__global__ __launch_bounds__(256) void k_gemm_nt(const float* __restrict__ A,
                                                 const float* __restrict__ Bm,
                                                 const float* __restrict__ bias,
                                                 float* __restrict__ C,
                                                 int N, int K, int useBias) {
    __shared__ float As[16][68];
    __shared__ float Bs[16][68];
    int m0 = blockIdx.x * 64;
    int n0 = blockIdx.y * 64;
    int tid = threadIdx.x;
    int lr = tid >> 2;
    int lk = (tid & 3) << 2;
    int tx = tid & 15, ty = tid >> 4;
    u64 acc2[4][2];
#pragma unroll
    for (int i = 0; i < 4; i++) { acc2[i][0] = 0ULL; acc2[i][1] = 0ULL; }
    const float* aPtr = A + (size_t)(m0 + lr) * K + lk;
    const float* bPtr = Bm + (size_t)(n0 + lr) * K + lk;
    for (int k0 = 0; k0 < K; k0 += 16) {
        float4 av = *(const float4*)(aPtr + k0);
        float4 bv = *(const float4*)(bPtr + k0);
        __syncthreads();
        As[lk + 0][lr] = av.x; As[lk + 1][lr] = av.y; As[lk + 2][lr] = av.z; As[lk + 3][lr] = av.w;
        Bs[lk + 0][lr] = bv.x; Bs[lk + 1][lr] = bv.y; Bs[lk + 2][lr] = bv.z; Bs[lk + 3][lr] = bv.w;
        __syncthreads();
#pragma unroll
        for (int kk = 0; kk < 16; kk++) {
            float4 a = *(const float4*)&As[kk][ty * 4];
            float4 bq = *(const float4*)&Bs[kk][tx * 4];
            u64 pb0 = pk2(bq.x, bq.y), pb1 = pk2(bq.z, bq.w);
            float ar[4] = {a.x, a.y, a.z, a.w};
#pragma unroll
            for (int i = 0; i < 4; i++) {
                u64 pa = pk2(ar[i], ar[i]);
                ffma2(acc2[i][0], pb0, pa);
                ffma2(acc2[i][1], pb1, pa);
            }
        }
    }
#pragma unroll
    for (int i = 0; i < 4; i++) {
        int m = m0 + ty * 4 + i;
        float v[4];
        upk2(acc2[i][0], v[0], v[1]);
        upk2(acc2[i][1], v[2], v[3]);
#pragma unroll
        for (int j = 0; j < 4; j++) {
            int n = n0 + tx * 4 + j;
            float val = v[j];
            if (useBias) val += bias[n];
            C[(size_t)m * N + n] = val;
        }
    }
}

// ================= codebook norms =================
__global__ void k_cnorm(const float* __restrict__ cb) {
    int j = blockIdx.x * blockDim.x + threadIdx.x;
    if (j < 1024) {
        float s = 0.f;
        const float* c = cb + (size_t)j * 128;
#pragma unroll 8
        for (int k = 0; k < 128; k++) s = fmaf(c[k], c[k], s);
        g_cnorm[j] = s;
    }
}

// ================= argmin over codewords + gather z_q =================
__global__ __launch_bounds__(128) void k_argmin_gather(const float* __restrict__ cb) {
    __shared__ float sv[128];
    __shared__ int si[128];
    int img = blockIdx.x;
    int tid = threadIdx.x;
    const float* srow = g_scores + (size_t)img * 1024;
    float best = 3.4e38f;
    int bi = 0;
    for (int j = tid; j < 1024; j += 128) {
        float v = g_cnorm[j] - 2.f * srow[j];
        if (v < best) { best = v; bi = j; }
    }
    sv[tid] = best; si[tid] = bi;
    __syncthreads();
    for (int s = 64; s > 0; s >>= 1) {
        if (tid < s) {
            float v2 = sv[tid + s]; int i2 = si[tid + s];
            if (v2 < sv[tid] || (v2 == sv[tid] && i2 < si[tid])) { sv[tid] = v2; si[tid] = i2; }
        }
        __syncthreads();
    }
    int idx = si[0];
    g_zq[(size_t)img * 128 + tid] = cb[(size_t)idx * 128 + tid];
}

// ================= build fused matrix M[576,128] = Weff_dct1 o dec_fc_w, cvec[576] =================
// dec_fc and dct1 compose (no nonlinearity between them).
__global__ __launch_bounds__(128) void k_buildM(const float* __restrict__ w1,
                                                const float* __restrict__ b1,
                                                const float* __restrict__ decw,
                                                const float* __restrict__ decb) {
    __shared__ float swt[128 * 9];
    __shared__ int sq[9];
    __shared__ int skk[9];
    __shared__ int snt;
    int row = blockIdx.x;
    int oc = row / 9, pp = row - oc * 9, py = pp / 3, px = pp - py * 3;
    int l = threadIdx.x;
    if (l == 0) {
        int nt = 0;
        for (int ky = 0; ky < 3; ky++)
            for (int kx = 0; kx < 3; kx++) {
                int qy = py + ky - 1, qx = px + kx - 1;
                if (qy >= 0 && qy < 3 && qx >= 0 && qx < 3) {
                    sq[nt] = qy * 3 + qx;
                    skk[nt] = ky * 3 + kx;
                    nt++;
                }
            }
        snt = nt;
    }
    __syncthreads();
    int nt = snt;
    for (int idx = l; idx < 128 * nt; idx += 128) {
        int ic = idx / nt, t = idx - ic * nt;
        // Weff[oc][ic][ky][kx] = dct1_w[ic][oc][2-ky][2-kx]
        swt[idx] = w1[ic * 576 + oc * 9 + (8 - skk[t])];
    }
    __syncthreads();
    float acc = 0.f;
    for (int ic = 0; ic < 128; ic++) {
        const float* dr = decw + (size_t)ic * 9 * 128 + l;
        const float* wr = swt + ic * nt;
        for (int t = 0; t < nt; t++)
            acc = fmaf(wr[t], dr[(size_t)sq[t] * 128], acc);
    }
    g_M[row * 128 + l] = acc;
    if (l == 0) {
        float ab = 0.f;
        for (int ic = 0; ic < 128; ic++)
            for (int t = 0; t < nt; t++)
                ab = fmaf(swt[ic * nt + t], decb[ic * 9 + sq[t]], ab);
        g_cv[row] = ab + b1[oc];
    }
}

// ================= fused dec_fc+dct1: g_d1 = upsample2(relu(zq @ M^T + cvec)) =================
// GEMM M=8192, N=576, K=128 with relu+upsample epilogue.
__global__ __launch_bounds__(256) void k_fc1() {
    __shared__ float As[16][68];
    __shared__ float Bs[16][68];
    int m0 = blockIdx.x * 64;
    int n0 = blockIdx.y * 64;
    int tid = threadIdx.x;
    int lr = tid >> 2;
    int lk = (tid & 3) << 2;
    int tx = tid & 15, ty = tid >> 4;
    u64 acc2[4][2];
#pragma unroll
    for (int i = 0; i < 4; i++) { acc2[i][0] = 0ULL; acc2[i][1] = 0ULL; }
    const float* aPtr = g_zq + (size_t)(m0 + lr) * 128 + lk;
    const float* bPtr = g_M + (size_t)(n0 + lr) * 128 + lk;
    for (int k0 = 0; k0 < 128; k0 += 16) {
        float4 av = *(const float4*)(aPtr + k0);
        float4 bv = *(const float4*)(bPtr + k0);
        __syncthreads();
        As[lk + 0][lr] = av.x; As[lk + 1][lr] = av.y; As[lk + 2][lr] = av.z; As[lk + 3][lr] = av.w;
        Bs[lk + 0][lr] = bv.x; Bs[lk + 1][lr] = bv.y; Bs[lk + 2][lr] = bv.z; Bs[lk + 3][lr] = bv.w;
        __syncthreads();
#pragma unroll
        for (int kk = 0; kk < 16; kk++) {
            float4 a = *(const float4*)&As[kk][ty * 4];
            float4 bq = *(const float4*)&Bs[kk][tx * 4];
            u64 pb0 = pk2(bq.x, bq.y), pb1 = pk2(bq.z, bq.w);
            float ar[4] = {a.x, a.y, a.z, a.w};
#pragma unroll
            for (int i = 0; i < 4; i++) {
                u64 pa = pk2(ar[i], ar[i]);
                ffma2(acc2[i][0], pb0, pa);
                ffma2(acc2[i][1], pb1, pa);
            }
        }
    }
#pragma unroll
    for (int i = 0; i < 4; i++) {
        int m = m0 + ty * 4 + i;
        float v[4];
        upk2(acc2[i][0], v[0], v[1]);
        upk2(acc2[i][1], v[2], v[3]);
#pragma unroll
        for (int j = 0; j < 4; j++) {
            int n = n0 + tx * 4 + j;
            float val = fmaxf(v[j] + g_cv[n], 0.f);
            int oc = n / 9, pp = n - oc * 9;
            int py = pp / 3, px = pp - py * 3;
            float* o = g_d1 + ((size_t)m * 64 + oc) * 36 + py * 12 + px * 2;
            o[0] = val; o[1] = val; o[6] = val; o[7] = val;
        }
    }
}

// ================= dct2 (64->32, 6x6) conv-transpose + relu + up2 -> [B,32,12,12] =================
// 8 images/block, 384 threads = (img 8) x (octile of 4 oc: 8) x (row 6). f32x2 FMA.
__global__ __launch_bounds__(384) void k_dct2(const float* __restrict__ w,
                                              const float* __restrict__ b) {
    extern __shared__ float sm[];
    float* sIn = sm;                // 8 * 2304 = 18432
    float* sW  = sm + 18432;        // 576 taps * pitch 36 = 20736 (flipped)
    float* sB  = sW + 20736;        // 32
    int blk = blockIdx.x;           // 1024
    int tid = threadIdx.x;
    for (int i = tid; i < 8 * 2304; i += 384)
        sIn[i] = g_d1[(size_t)blk * 8 * 2304 + i];
    for (int i = tid; i < 64 * 288; i += 384) {
        int ic = i / 288, r2 = i - ic * 288;
        int oc = r2 / 9, g = r2 - oc * 9;
        sW[(ic * 9 + 8 - g) * 36 + oc] = w[i];
    }
    if (tid < 32) sB[tid] = b[tid];
    __syncthreads();
    int im = tid / 48;
    int r = tid - im * 48;
    int octile = r & 7;             // 8 octiles of 4 oc
    int y = r >> 3;                 // 0..5
    const float* sip = sIn + im * 2304;
    u64 acc2[6][2];
#pragma unroll
    for (int xq = 0; xq < 6; xq++) { acc2[xq][0] = 0ULL; acc2[xq][1] = 0ULL; }
    for (int ic = 0; ic < 64; ic++) {
#pragma unroll
        for (int ky = 0; ky < 3; ky++) {
            int yy = y + ky - 1;
            bool rowv = (yy >= 0) && (yy < 6);
            float in8[8];
#pragma unroll
            for (int j = 0; j < 8; j++) {
                int xx = j - 1;
                in8[j] = (rowv && xx >= 0 && xx < 6) ? sip[ic * 36 + yy * 6 + xx] : 0.f;
            }
            u64 pin[8];
#pragma unroll
            for (int j = 0; j < 8; j++) pin[j] = pk2(in8[j], in8[j]);
#pragma unroll
            for (int kx = 0; kx < 3; kx++) {
                const u64* wq = reinterpret_cast<const u64*>(sW + (ic * 9 + ky * 3 + kx) * 36) + octile * 2;
                u64 w01 = wq[0], w23 = wq[1];
#pragma unroll
                for (int xq = 0; xq < 6; xq++) {
                    ffma2(acc2[xq][0], w01, pin[xq + kx]);
                    ffma2(acc2[xq][1], w23, pin[xq + kx]);
                }
            }
        }
    }
#pragma unroll
    for (int j = 0; j < 2; j++) {
        int oc = octile * 4 + 2 * j;
        float blo = sB[oc], bhi = sB[oc + 1];
        float* olo = g_d2 + ((size_t)(blk * 8 + im) * 32 + oc) * 144;
        float* ohi = olo + 144;
#pragma unroll
        for (int xq = 0; xq < 6; xq++) {
            float vl, vh;
            upk2(acc2[xq][j], vl, vh);
            vl = fmaxf(vl + blo, 0.f);
            vh = fmaxf(vh + bhi, 0.f);
            int rb = (2 * y) * 12 + 2 * xq;
            olo[rb] = vl; olo[rb + 1] = vl; olo[rb + 12] = vl; olo[rb + 13] = vl;
            ohi[rb] = vh; ohi[rb + 1] = vh; ohi[rb + 12] = vh; ohi[rb + 13] = vh;
        }
    }
}

// ================= dct3 (32->1, 12x12) conv-transpose + relu + up2 -> d_out [B,1,24,24] =================
__global__ __launch_bounds__(192) void k_dct3(const float* __restrict__ w,
                                              const float* __restrict__ b,
                                              float* __restrict__ out) {
    extern __shared__ float sm[];
    float* sIn = sm;                // 8 * 4608 = 36864
    float* sW  = sm + 36864;        // 288
    int blk = blockIdx.x;           // 1024
    int tid = threadIdx.x;
    for (int i = tid; i < 8 * 4608; i += 192)
        sIn[i] = g_d2[(size_t)blk * 8 * 4608 + i];
    for (int i = tid; i < 288; i += 192) {
        int ic = i / 9, k = i - ic * 9;
        sW[ic * 9 + k] = w[ic * 9 + (8 - k)];
    }
    __syncthreads();
    float b0 = b[0];
    int im = tid / 24;
    int r = tid - im * 24;
    int y = r >> 1;                 // 0..11
    int xh = (r & 1) * 6;           // x base: 0 or 6
    const float* sip = sIn + im * 4608;
    float acc[6];
#pragma unroll
    for (int xq = 0; xq < 6; xq++) acc[xq] = 0.f;
    for (int ic = 0; ic < 32; ic++) {
#pragma unroll
        for (int ky = 0; ky < 3; ky++) {
            int yy = y + ky - 1;
            bool rowv = (yy >= 0) && (yy < 12);
            float in8[8];
#pragma unroll
            for (int j = 0; j < 8; j++) {
                int xx = xh + j - 1;
                in8[j] = (rowv && xx >= 0 && xx < 12) ? sip[ic * 144 + yy * 12 + xx] : 0.f;
            }
            float w3[3];
#pragma unroll
            for (int kx = 0; kx < 3; kx++) w3[kx] = sW[ic * 9 + ky * 3 + kx];
#pragma unroll
            for (int xq = 0; xq < 6; xq++)
#pragma unroll
                for (int kx = 0; kx < 3; kx++)
                    acc[xq] = fmaf(in8[xq + kx], w3[kx], acc[xq]);
        }
    }
    float* o = out + (size_t)(blk * 8 + im) * 576;
#pragma unroll
    for (int xq = 0; xq < 6; xq++) {
        float v = fmaxf(acc[xq] + b0, 0.f);
        int gx = xh + xq;
        int rb = (2 * y) * 24 + 2 * gx;
        o[rb] = v; o[rb + 1] = v; o[rb + 24] = v; o[rb + 25] = v;
    }
}

// ================= launcher =================
extern "C" void kernel_launch(void* const* d_in, const int* in_sizes, int n_in,
                              void* d_out, int out_size) {
    (void)in_sizes; (void)n_in; (void)out_size;
    const float* x    = (const float*)d_in[0];
    const float* c1w  = (const float*)d_in[1];
    const float* c1b  = (const float*)d_in[2];
    const float* c2w  = (const float*)d_in[3];
    const float* c2b  = (const float*)d_in[4];
    const float* c3w  = (const float*)d_in[5];
    const float* c3b  = (const float*)d_in[6];
    const float* encw = (const float*)d_in[7];
    const float* encb = (const float*)d_in[8];
    const float* cb   = (const float*)d_in[9];
    const float* decw = (const float*)d_in[10];
    const float* decb = (const float*)d_in[11];
    const float* d1w  = (const float*)d_in[12];
    const float* d1b  = (const float*)d_in[13];
    const float* d2w  = (const float*)d_in[14];
    const float* d2b  = (const float*)d_in[15];
    const float* d3w  = (const float*)d_in[16];
    const float* d3b  = (const float*)d_in[17];
    float* out = (float*)d_out;

    cudaFuncSetAttribute(k_conv2, cudaFuncAttributeMaxDynamicSharedMemorySize, 103680);
    cudaFuncSetAttribute(k_conv3, cudaFuncAttributeMaxDynamicSharedMemorySize, 214528);
    cudaFuncSetAttribute(k_dct2,  cudaFuncAttributeMaxDynamicSharedMemorySize, 156800);
    cudaFuncSetAttribute(k_dct3,  cudaFuncAttributeMaxDynamicSharedMemorySize, 148608);

    float *p_h3, *p_z, *p_scores;
    cudaGetSymbolAddress((void**)&p_h3, g_h3);
    cudaGetSymbolAddress((void**)&p_z, g_z);
    cudaGetSymbolAddress((void**)&p_scores, g_scores);

    k_conv1<<<BATCH, 256>>>(x, c1w, c1b);
    k_cnorm<<<4, 256>>>(cb);
    k_buildM<<<576, 128>>>(d1w, d1b, decw, decb);
    k_conv2<<<BATCH, 288, 103680>>>(c2w, c2b);
    k_conv3<<<BATCH / 8, 576, 214528>>>(c3w, c3b);
    // z = h3 @ encw^T + encb   [8192,1152]x[128,1152]^T
    k_gemm_nt<<<dim3(BATCH / 64, 2), 256>>>(p_h3, encw, encb, p_z, 128, 1152, 1);
    // scores = z @ cb^T        [8192,128]x[1024,128]^T
    k_gemm_nt<<<dim3(BATCH / 64, 16), 256>>>(p_z, cb, nullptr, p_scores, 1024, 128, 0);
    k_argmin_gather<<<BATCH, 128>>>(cb);
    // fused dec_fc + dct1 + relu + upsample
    k_fc1<<<dim3(BATCH / 64, 9), 256>>>();
    k_dct2<<<BATCH / 8, 384, 156800>>>(d2w, d2b);
    k_dct3<<<BATCH / 8, 192, 148608>>>(d3w, d3b, out);
}